// round 1
// baseline (speedup 1.0000x reference)
#include <cuda_runtime.h>
#include <cstdint>

#define BATCH 2
#define SEQ   2048
#define DM    1024
#define DS    16
#define MTOT  (BATCH*SEQ)   // 4096

// Scratch (device globals — no allocation allowed)
__device__ float g_delta [MTOT*DM];       // (b,l,d)  softplus(x @ W_dt^T + b_dt)
__device__ float g_deltaT[BATCH*DM*SEQ];  // (b,d,l)
__device__ float g_xT    [BATCH*DM*SEQ];  // (b,d,l)
__device__ float g_Bt    [BATCH*DS*SEQ];  // (b,n,l)
__device__ float g_Ct    [BATCH*DS*SEQ];  // (b,n,l)
__device__ float g_yT    [BATCH*DM*SEQ];  // (b,d,l)

__device__ __forceinline__ float softplus_f(float z) {
    return fmaxf(z, 0.f) + log1pf(expf(-fabsf(z)));
}

// ---------------------------------------------------------------------------
// Kernel 1: delta = softplus(x @ W_dt^T + b_dt)
// NT fp32 SGEMM: M=4096, N=1024, K=1024. BM=128, BN=64, BK=16, 256 thr, 8x4 micro.
// ---------------------------------------------------------------------------
__global__ __launch_bounds__(256) void gemm_delta_kernel(
    const float* __restrict__ X,    // (4096,1024)
    const float* __restrict__ W,    // (1024,1024) row-major (out,in)
    const float* __restrict__ bias) // (1024)
{
    __shared__ float As[16][132];
    __shared__ float Bs[16][68];

    const int tid = threadIdx.x;
    const int m0 = blockIdx.y * 128;
    const int n0 = blockIdx.x * 64;
    const int tx = tid & 15;   // n microtile index
    const int ty = tid >> 4;   // m microtile index

    float acc[8][4];
#pragma unroll
    for (int i = 0; i < 8; i++)
#pragma unroll
        for (int j = 0; j < 4; j++) acc[i][j] = 0.f;

    const int lrow = tid >> 2;
    const int lc4  = (tid & 3) * 4;

    for (int k0 = 0; k0 < DM; k0 += 16) {
        // load A tile 128x16 (2 float4 per thread), store transposed
#pragma unroll
        for (int r = 0; r < 2; r++) {
            int row = lrow + r * 64;
            float4 v = *(const float4*)(X + (size_t)(m0 + row) * DM + k0 + lc4);
            As[lc4 + 0][row] = v.x; As[lc4 + 1][row] = v.y;
            As[lc4 + 2][row] = v.z; As[lc4 + 3][row] = v.w;
        }
        // load B tile 64x16 (1 float4 per thread), store transposed
        {
            float4 v = *(const float4*)(W + (size_t)(n0 + lrow) * DM + k0 + lc4);
            Bs[lc4 + 0][lrow] = v.x; Bs[lc4 + 1][lrow] = v.y;
            Bs[lc4 + 2][lrow] = v.z; Bs[lc4 + 3][lrow] = v.w;
        }
        __syncthreads();
#pragma unroll
        for (int kk = 0; kk < 16; kk++) {
            float a[8], bb[4];
            *(float4*)(a)     = *(const float4*)&As[kk][ty * 8];
            *(float4*)(a + 4) = *(const float4*)&As[kk][ty * 8 + 4];
            *(float4*)(bb)    = *(const float4*)&Bs[kk][tx * 4];
#pragma unroll
            for (int i = 0; i < 8; i++)
#pragma unroll
                for (int j = 0; j < 4; j++)
                    acc[i][j] = fmaf(a[i], bb[j], acc[i][j]);
        }
        __syncthreads();
    }

    float4 bv = *(const float4*)(bias + n0 + tx * 4);
#pragma unroll
    for (int i = 0; i < 8; i++) {
        float4 o;
        o.x = softplus_f(acc[i][0] + bv.x);
        o.y = softplus_f(acc[i][1] + bv.y);
        o.z = softplus_f(acc[i][2] + bv.z);
        o.w = softplus_f(acc[i][3] + bv.w);
        *(float4*)(g_delta + (size_t)(m0 + ty * 8 + i) * DM + n0 + tx * 4) = o;
    }
}

// ---------------------------------------------------------------------------
// Kernel 2: Bv/Cv projections -> transposed (b, n, l) layout.
// One warp per sequence position m. 32 outputs (16 B + 16 C) per warp.
// ---------------------------------------------------------------------------
__global__ __launch_bounds__(128) void bc_kernel(
    const float* __restrict__ X,
    const float* __restrict__ WB, const float* __restrict__ bB,
    const float* __restrict__ WC, const float* __restrict__ bC)
{
    const int warp = threadIdx.x >> 5;
    const int lane = threadIdx.x & 31;
    const int m = blockIdx.x * 4 + warp;     // 0..4095
    const int b = m >> 11;
    const int l = m & (SEQ - 1);

    float accB[16], accC[16];
#pragma unroll
    for (int j = 0; j < 16; j++) { accB[j] = 0.f; accC[j] = 0.f; }

    const float4* X4  = (const float4*)(X + (size_t)m * DM);
    const float4* WB4 = (const float4*)WB;
    const float4* WC4 = (const float4*)WC;

    for (int k0 = 0; k0 < DM / 4; k0 += 32) {
        float4 xv = X4[k0 + lane];
#pragma unroll
        for (int j = 0; j < 16; j++) {
            float4 w = WB4[j * (DM / 4) + k0 + lane];
            accB[j] += xv.x * w.x + xv.y * w.y + xv.z * w.z + xv.w * w.w;
            float4 wc = WC4[j * (DM / 4) + k0 + lane];
            accC[j] += xv.x * wc.x + xv.y * wc.y + xv.z * wc.z + xv.w * wc.w;
        }
    }

    float res = 0.f;
#pragma unroll
    for (int j = 0; j < 32; j++) {
        float p = (j < 16) ? accB[j] : accC[j - 16];
#pragma unroll
        for (int o = 16; o > 0; o >>= 1)
            p += __shfl_xor_sync(0xffffffffu, p, o);
        if (lane == j) res = p;
    }
    if (lane < 16)
        g_Bt[(size_t)(b * DS + lane) * SEQ + l] = res + bB[lane];
    else
        g_Ct[(size_t)(b * DS + (lane - 16)) * SEQ + l] = res + bC[lane - 16];
}

// ---------------------------------------------------------------------------
// Kernel 3: transpose delta and x from (b,l,d) -> (b,d,l)
// ---------------------------------------------------------------------------
__global__ void transpose2_kernel(const float* __restrict__ X)
{
    __shared__ float t0[32][33];
    __shared__ float t1[32][33];
    const int b  = blockIdx.z;
    const int d0 = blockIdx.x * 32;
    const int l0 = blockIdx.y * 32;
    const int tx = threadIdx.x, ty = threadIdx.y;

#pragma unroll
    for (int i = 0; i < 32; i += 8) {
        size_t src = ((size_t)(b * SEQ + l0 + ty + i)) * DM + d0 + tx;
        t0[ty + i][tx] = g_delta[src];
        t1[ty + i][tx] = X[src];
    }
    __syncthreads();
#pragma unroll
    for (int i = 0; i < 32; i += 8) {
        size_t dst = ((size_t)(b * DM + d0 + ty + i)) * SEQ + l0 + tx;
        g_deltaT[dst] = t0[tx][ty + i];
        g_xT[dst]     = t1[tx][ty + i];
    }
}

// ---------------------------------------------------------------------------
// Kernel 4: the SSM scan. 16-lane group per (b,d); lane n holds state h[n].
//   h = exp(delta*A[d,n]) * h + delta * B[l,n] * x
//   y[l] = sum_n h * C[l,n]   (4-level butterfly within the 16-lane group)
// float4 over 4 timesteps per load. Writes yT (b,d,l).
// ---------------------------------------------------------------------------
__global__ __launch_bounds__(128) void scan_kernel(const float* __restrict__ logA)
{
    const int gid = blockIdx.x * 8 + (threadIdx.x >> 4); // (b,d): 0..2047
    const int b = gid >> 10;
    const int d = gid & (DM - 1);
    const int n = threadIdx.x & 15;

    const float A = -expf(logA[d * DS + n]);

    const float4* dp = (const float4*)(g_deltaT + ((size_t)b * DM + d) * SEQ);
    const float4* xp = (const float4*)(g_xT     + ((size_t)b * DM + d) * SEQ);
    const float4* bp = (const float4*)(g_Bt     + ((size_t)b * DS + n) * SEQ);
    const float4* cp = (const float4*)(g_Ct     + ((size_t)b * DS + n) * SEQ);
    float4*       yp = (float4*)(g_yT           + ((size_t)b * DM + d) * SEQ);

    float h = 0.f;

#define SSM_STEP(DV, XV, BV, CV, YO)                                   \
    {                                                                  \
        float dA = __expf((DV) * A);                                   \
        h = fmaf(dA, h, (DV) * (XV) * (BV));                           \
        float p = h * (CV);                                            \
        p += __shfl_xor_sync(0xffffffffu, p, 8);                       \
        p += __shfl_xor_sync(0xffffffffu, p, 4);                       \
        p += __shfl_xor_sync(0xffffffffu, p, 2);                       \
        p += __shfl_xor_sync(0xffffffffu, p, 1);                       \
        (YO) = p;                                                      \
    }

    for (int q = 0; q < SEQ / 4; q++) {
        float4 dv = dp[q], xv = xp[q], bv = bp[q], cv = cp[q];
        float4 y;
        SSM_STEP(dv.x, xv.x, bv.x, cv.x, y.x);
        SSM_STEP(dv.y, xv.y, bv.y, cv.y, y.y);
        SSM_STEP(dv.z, xv.z, bv.z, cv.z, y.z);
        SSM_STEP(dv.w, xv.w, bv.w, cv.w, y.w);
        if (n == 0) yp[q] = y;
    }
#undef SSM_STEP
}

// ---------------------------------------------------------------------------
// Kernel 5: out[b,l,d] = yT[b,d,l] + x[b,l,d] * D_skip[d]
// ---------------------------------------------------------------------------
__global__ void out_kernel(const float* __restrict__ X,
                           const float* __restrict__ Dskip,
                           float* __restrict__ out)
{
    __shared__ float t[32][33];
    const int b  = blockIdx.z;
    const int l0 = blockIdx.x * 32;
    const int d0 = blockIdx.y * 32;
    const int tx = threadIdx.x, ty = threadIdx.y;

#pragma unroll
    for (int i = 0; i < 32; i += 8)
        t[ty + i][tx] = g_yT[((size_t)(b * DM + d0 + ty + i)) * SEQ + l0 + tx];
    __syncthreads();
    const float dsk = Dskip[d0 + tx];
#pragma unroll
    for (int i = 0; i < 32; i += 8) {
        size_t idx = ((size_t)(b * SEQ + l0 + ty + i)) * DM + d0 + tx;
        out[idx] = t[tx][ty + i] + X[idx] * dsk;
    }
}

// ---------------------------------------------------------------------------
extern "C" void kernel_launch(void* const* d_in, const int* in_sizes, int n_in,
                              void* d_out, int out_size)
{
    (void)in_sizes; (void)n_in; (void)out_size;
    const float* x    = (const float*)d_in[0];
    const float* W_B  = (const float*)d_in[1];
    const float* b_B  = (const float*)d_in[2];
    const float* W_C  = (const float*)d_in[3];
    const float* b_C  = (const float*)d_in[4];
    const float* W_dt = (const float*)d_in[5];
    const float* b_dt = (const float*)d_in[6];
    const float* logA = (const float*)d_in[7];
    const float* Dsk  = (const float*)d_in[8];
    float* out = (float*)d_out;

    gemm_delta_kernel<<<dim3(DM / 64, MTOT / 128), 256>>>(x, W_dt, b_dt);
    bc_kernel<<<MTOT / 4, 128>>>(x, W_B, b_B, W_C, b_C);
    transpose2_kernel<<<dim3(DM / 32, SEQ / 32, BATCH), dim3(32, 8)>>>(x);
    scan_kernel<<<(BATCH * DM) / 8, 128>>>(logA);
    out_kernel<<<dim3(SEQ / 32, DM / 32, BATCH), dim3(32, 8)>>>(x, Dsk, out);
}

// round 2
// speedup vs baseline: 1.3661x; 1.3661x over previous
#include <cuda_runtime.h>
#include <cstdint>

#define BATCH 2
#define SEQ   2048
#define DM    1024
#define DS    16
#define MTOT  (BATCH*SEQ)   // 4096
#define CH    16            // scan chunks
#define CS    (SEQ/CH)      // 128 steps per chunk

// Scratch (device globals — no allocation allowed)
__device__ float g_delta [MTOT*DM];       // (b,l,d)
__device__ float g_deltaT[BATCH*DM*SEQ];  // (b,d,l)
__device__ float g_xT    [BATCH*DM*SEQ];  // (b,d,l)
__device__ float g_B     [MTOT*DS];       // (b,l,n)
__device__ float g_C     [MTOT*DS];       // (b,l,n)
__device__ float g_yT    [BATCH*DM*SEQ];  // (b,d,l)
__device__ float g_P     [BATCH*DM*CH*DS];
__device__ float g_q     [BATCH*DM*CH*DS];
__device__ float g_h0    [BATCH*DM*CH*DS];

__device__ __forceinline__ float softplus_f(float z) {
    return fmaxf(z, 0.f) + log1pf(expf(-fabsf(z)));
}

// ---------------------------------------------------------------------------
// Kernel 1: delta = softplus(x @ W_dt^T + b_dt)
// NT fp32 GEMM, 128x128 tile, BK=8, double-buffered smem, packed fma.rn.f32x2.
// ---------------------------------------------------------------------------
__global__ __launch_bounds__(256) void gemm_delta_kernel(
    const float* __restrict__ X,    // (4096,1024)
    const float* __restrict__ W,    // (1024,1024) (out,in)
    const float* __restrict__ bias)
{
    __shared__ __align__(16) float As[2][8][132];
    __shared__ __align__(16) float Bs[2][8][132];

    const int tid = threadIdx.x;
    const int m0 = blockIdx.y * 128;
    const int n0 = blockIdx.x * 128;
    const int tx = tid & 15;   // n micro index
    const int ty = tid >> 4;   // m micro index

    const int lrow = tid >> 1;        // 0..127
    const int lcol = (tid & 1) * 4;   // 0 or 4

    const float* Aptr = X + (size_t)(m0 + lrow) * DM + lcol;
    const float* Bptr = W + (size_t)(n0 + lrow) * DM + lcol;

    // acc[i][j] = packed f32x2 for rows m0+ty*8+i, cols n0+tx*8+{2j,2j+1}
    unsigned long long acc[8][4];
#pragma unroll
    for (int i = 0; i < 8; i++)
#pragma unroll
        for (int j = 0; j < 4; j++) acc[i][j] = 0ull;

    float4 av = *(const float4*)(Aptr);
    float4 bv = *(const float4*)(Bptr);
    As[0][lcol + 0][lrow] = av.x; As[0][lcol + 1][lrow] = av.y;
    As[0][lcol + 2][lrow] = av.z; As[0][lcol + 3][lrow] = av.w;
    Bs[0][lcol + 0][lrow] = bv.x; Bs[0][lcol + 1][lrow] = bv.y;
    Bs[0][lcol + 2][lrow] = bv.z; Bs[0][lcol + 3][lrow] = bv.w;
    __syncthreads();

    for (int it = 0; it < DM / 8; it++) {
        const int cur = it & 1;
        if (it < DM / 8 - 1) {
            av = *(const float4*)(Aptr + (it + 1) * 8);
            bv = *(const float4*)(Bptr + (it + 1) * 8);
        }
#pragma unroll
        for (int kk = 0; kk < 8; kk++) {
            float a[8];
            *(float4*)(a)     = *(const float4*)&As[cur][kk][ty * 8];
            *(float4*)(a + 4) = *(const float4*)&As[cur][kk][ty * 8 + 4];
            ulonglong2 b01 = *(const ulonglong2*)&Bs[cur][kk][tx * 8];
            ulonglong2 b23 = *(const ulonglong2*)&Bs[cur][kk][tx * 8 + 4];
            unsigned long long bb0 = b01.x, bb1 = b01.y, bb2 = b23.x, bb3 = b23.y;
#pragma unroll
            for (int i = 0; i < 8; i++) {
                unsigned long long aa;
                asm("mov.b64 %0, {%1, %1};" : "=l"(aa) : "r"(__float_as_uint(a[i])));
                asm("fma.rn.f32x2 %0, %1, %2, %0;" : "+l"(acc[i][0]) : "l"(aa), "l"(bb0));
                asm("fma.rn.f32x2 %0, %1, %2, %0;" : "+l"(acc[i][1]) : "l"(aa), "l"(bb1));
                asm("fma.rn.f32x2 %0, %1, %2, %0;" : "+l"(acc[i][2]) : "l"(aa), "l"(bb2));
                asm("fma.rn.f32x2 %0, %1, %2, %0;" : "+l"(acc[i][3]) : "l"(aa), "l"(bb3));
            }
        }
        if (it < DM / 8 - 1) {
            const int nxt = cur ^ 1;
            As[nxt][lcol + 0][lrow] = av.x; As[nxt][lcol + 1][lrow] = av.y;
            As[nxt][lcol + 2][lrow] = av.z; As[nxt][lcol + 3][lrow] = av.w;
            Bs[nxt][lcol + 0][lrow] = bv.x; Bs[nxt][lcol + 1][lrow] = bv.y;
            Bs[nxt][lcol + 2][lrow] = bv.z; Bs[nxt][lcol + 3][lrow] = bv.w;
        }
        __syncthreads();
    }

    float bias8[8];
    *(float4*)(bias8)     = *(const float4*)(bias + n0 + tx * 8);
    *(float4*)(bias8 + 4) = *(const float4*)(bias + n0 + tx * 8 + 4);
#pragma unroll
    for (int i = 0; i < 8; i++) {
        float o[8];
#pragma unroll
        for (int j = 0; j < 4; j++) {
            unsigned int lo, hi;
            asm("mov.b64 {%0, %1}, %2;" : "=r"(lo), "=r"(hi) : "l"(acc[i][j]));
            o[2 * j]     = softplus_f(__uint_as_float(lo) + bias8[2 * j]);
            o[2 * j + 1] = softplus_f(__uint_as_float(hi) + bias8[2 * j + 1]);
        }
        float* dst = g_delta + (size_t)(m0 + ty * 8 + i) * DM + n0 + tx * 8;
        *(float4*)(dst)     = *(float4*)(o);
        *(float4*)(dst + 4) = *(float4*)(o + 4);
    }
}

// ---------------------------------------------------------------------------
// Kernel 2: B/C projections -> (b, l, n) layout (no transpose needed).
// ---------------------------------------------------------------------------
__global__ __launch_bounds__(128) void bc_kernel(
    const float* __restrict__ X,
    const float* __restrict__ WB, const float* __restrict__ bB,
    const float* __restrict__ WC, const float* __restrict__ bC)
{
    const int warp = threadIdx.x >> 5;
    const int lane = threadIdx.x & 31;
    const int m = blockIdx.x * 4 + warp;     // 0..4095 == b*SEQ + l

    float accB[16], accC[16];
#pragma unroll
    for (int j = 0; j < 16; j++) { accB[j] = 0.f; accC[j] = 0.f; }

    const float4* X4  = (const float4*)(X + (size_t)m * DM);
    const float4* WB4 = (const float4*)WB;
    const float4* WC4 = (const float4*)WC;

    for (int k0 = 0; k0 < DM / 4; k0 += 32) {
        float4 xv = X4[k0 + lane];
#pragma unroll
        for (int j = 0; j < 16; j++) {
            float4 w = WB4[j * (DM / 4) + k0 + lane];
            accB[j] += xv.x * w.x + xv.y * w.y + xv.z * w.z + xv.w * w.w;
            float4 wc = WC4[j * (DM / 4) + k0 + lane];
            accC[j] += xv.x * wc.x + xv.y * wc.y + xv.z * wc.z + xv.w * wc.w;
        }
    }

    float res = 0.f;
#pragma unroll
    for (int j = 0; j < 32; j++) {
        float p = (j < 16) ? accB[j] : accC[j - 16];
#pragma unroll
        for (int o = 16; o > 0; o >>= 1)
            p += __shfl_xor_sync(0xffffffffu, p, o);
        if (lane == j) res = p;
    }
    if (lane < 16)
        g_B[(size_t)m * DS + lane] = res + bB[lane];
    else
        g_C[(size_t)m * DS + (lane - 16)] = res + bC[lane - 16];
}

// ---------------------------------------------------------------------------
// Kernel 3: transpose delta and x from (b,l,d) -> (b,d,l)
// ---------------------------------------------------------------------------
__global__ void transpose2_kernel(const float* __restrict__ X)
{
    __shared__ float t0[32][33];
    __shared__ float t1[32][33];
    const int b  = blockIdx.z;
    const int d0 = blockIdx.x * 32;
    const int l0 = blockIdx.y * 32;
    const int tx = threadIdx.x, ty = threadIdx.y;

#pragma unroll
    for (int i = 0; i < 32; i += 8) {
        size_t src = ((size_t)(b * SEQ + l0 + ty + i)) * DM + d0 + tx;
        t0[ty + i][tx] = g_delta[src];
        t1[ty + i][tx] = X[src];
    }
    __syncthreads();
#pragma unroll
    for (int i = 0; i < 32; i += 8) {
        size_t dst = ((size_t)(b * DM + d0 + ty + i)) * SEQ + l0 + tx;
        g_deltaT[dst] = t0[tx][ty + i];
        g_xT[dst]     = t1[tx][ty + i];
    }
}

// ---------------------------------------------------------------------------
// Scan pass 1: per chunk, compute P = prod(dA) and q = h(end | h0=0).
// Block = 128 thr = 8 groups of 16 lanes, all sharing (b, chunk); d = d0..d0+7.
// Grid = (DM/8, CH, BATCH).
// ---------------------------------------------------------------------------
__global__ __launch_bounds__(128) void scan_pass1(const float* __restrict__ logA)
{
    __shared__ __align__(16) float sB[CS * DS];   // 8 KB

    const int b  = blockIdx.z;
    const int c  = blockIdx.y;
    const int d0 = blockIdx.x * 8;
    const int g  = threadIdx.x >> 4;
    const int n  = threadIdx.x & 15;
    const int d  = d0 + g;
    const int bd = b * DM + d;

    {   // cooperative load of this chunk's B tile (shared by all 8 groups)
        const float4* src = (const float4*)(g_B + ((size_t)b * SEQ + c * CS) * DS);
        float4* dst = (float4*)sB;
        for (int i = threadIdx.x; i < CS * DS / 4; i += 128) dst[i] = src[i];
    }
    __syncthreads();

    const float A = -expf(logA[d * DS + n]);
    const float4* dp = (const float4*)(g_deltaT + (size_t)bd * SEQ + c * CS);
    const float4* xp = (const float4*)(g_xT     + (size_t)bd * SEQ + c * CS);

    float h = 0.f, P = 1.f;
    for (int q4 = 0; q4 < CS / 4; q4++) {
        float4 dv = dp[q4], xv = xp[q4];
        const int l = q4 * 4;
        float b0 = sB[(l + 0) * DS + n], b1 = sB[(l + 1) * DS + n];
        float b2 = sB[(l + 2) * DS + n], b3 = sB[(l + 3) * DS + n];
        float dA;
        dA = __expf(dv.x * A); P *= dA; h = fmaf(dA, h, dv.x * xv.x * b0);
        dA = __expf(dv.y * A); P *= dA; h = fmaf(dA, h, dv.y * xv.y * b1);
        dA = __expf(dv.z * A); P *= dA; h = fmaf(dA, h, dv.z * xv.z * b2);
        dA = __expf(dv.w * A); P *= dA; h = fmaf(dA, h, dv.w * xv.w * b3);
    }
    const size_t idx = ((size_t)bd * CH + c) * DS + n;
    g_P[idx] = P;
    g_q[idx] = h;
}

// ---------------------------------------------------------------------------
// Scan pass 2: sequentially combine chunk summaries -> h0 per chunk. Tiny.
// ---------------------------------------------------------------------------
__global__ void scan_combine()
{
    const int t = blockIdx.x * 256 + threadIdx.x;  // 0..32767 = (bd, n)
    const int bd = t >> 4;
    const int n  = t & 15;
    float h = 0.f;
    for (int c = 0; c < CH; c++) {
        const size_t idx = ((size_t)bd * CH + c) * DS + n;
        g_h0[idx] = h;
        h = fmaf(g_P[idx], h, g_q[idx]);
    }
}

// ---------------------------------------------------------------------------
// Scan pass 3: rescan each chunk from its h0, emit y via 16-lane butterfly.
// ---------------------------------------------------------------------------
__global__ __launch_bounds__(128) void scan_pass3(const float* __restrict__ logA)
{
    __shared__ __align__(16) float sB[CS * DS];
    __shared__ __align__(16) float sC[CS * DS];

    const int b  = blockIdx.z;
    const int c  = blockIdx.y;
    const int d0 = blockIdx.x * 8;
    const int g  = threadIdx.x >> 4;
    const int n  = threadIdx.x & 15;
    const int d  = d0 + g;
    const int bd = b * DM + d;

    {
        const float4* srcB = (const float4*)(g_B + ((size_t)b * SEQ + c * CS) * DS);
        const float4* srcC = (const float4*)(g_C + ((size_t)b * SEQ + c * CS) * DS);
        float4* dstB = (float4*)sB;
        float4* dstC = (float4*)sC;
        for (int i = threadIdx.x; i < CS * DS / 4; i += 128) {
            dstB[i] = srcB[i];
            dstC[i] = srcC[i];
        }
    }
    __syncthreads();

    const float A = -expf(logA[d * DS + n]);
    const float4* dp = (const float4*)(g_deltaT + (size_t)bd * SEQ + c * CS);
    const float4* xp = (const float4*)(g_xT     + (size_t)bd * SEQ + c * CS);
    float4*       yp = (float4*)(g_yT           + (size_t)bd * SEQ + c * CS);

    float h = g_h0[((size_t)bd * CH + c) * DS + n];

#define SSM_STEP(DV, XV, BV, CV, YO)                                   \
    {                                                                  \
        float dA = __expf((DV) * A);                                   \
        h = fmaf(dA, h, (DV) * (XV) * (BV));                           \
        float p = h * (CV);                                            \
        p += __shfl_xor_sync(0xffffffffu, p, 8);                       \
        p += __shfl_xor_sync(0xffffffffu, p, 4);                       \
        p += __shfl_xor_sync(0xffffffffu, p, 2);                       \
        p += __shfl_xor_sync(0xffffffffu, p, 1);                       \
        (YO) = p;                                                      \
    }

    for (int q4 = 0; q4 < CS / 4; q4++) {
        float4 dv = dp[q4], xv = xp[q4];
        const int l = q4 * 4;
        float b0 = sB[(l + 0) * DS + n], b1 = sB[(l + 1) * DS + n];
        float b2 = sB[(l + 2) * DS + n], b3 = sB[(l + 3) * DS + n];
        float c0 = sC[(l + 0) * DS + n], c1 = sC[(l + 1) * DS + n];
        float c2 = sC[(l + 2) * DS + n], c3 = sC[(l + 3) * DS + n];
        float4 y;
        SSM_STEP(dv.x, xv.x, b0, c0, y.x);
        SSM_STEP(dv.y, xv.y, b1, c1, y.y);
        SSM_STEP(dv.z, xv.z, b2, c2, y.z);
        SSM_STEP(dv.w, xv.w, b3, c3, y.w);
        if (n == 0) yp[q4] = y;
    }
#undef SSM_STEP
}

// ---------------------------------------------------------------------------
// Kernel 5: out[b,l,d] = yT[b,d,l] + x[b,l,d] * D_skip[d]
// ---------------------------------------------------------------------------
__global__ void out_kernel(const float* __restrict__ X,
                           const float* __restrict__ Dskip,
                           float* __restrict__ out)
{
    __shared__ float t[32][33];
    const int b  = blockIdx.z;
    const int l0 = blockIdx.x * 32;
    const int d0 = blockIdx.y * 32;
    const int tx = threadIdx.x, ty = threadIdx.y;

#pragma unroll
    for (int i = 0; i < 32; i += 8)
        t[ty + i][tx] = g_yT[((size_t)(b * DM + d0 + ty + i)) * SEQ + l0 + tx];
    __syncthreads();
    const float dsk = Dskip[d0 + tx];
#pragma unroll
    for (int i = 0; i < 32; i += 8) {
        size_t idx = ((size_t)(b * SEQ + l0 + ty + i)) * DM + d0 + tx;
        out[idx] = t[tx][ty + i] + X[idx] * dsk;
    }
}

// ---------------------------------------------------------------------------
extern "C" void kernel_launch(void* const* d_in, const int* in_sizes, int n_in,
                              void* d_out, int out_size)
{
    (void)in_sizes; (void)n_in; (void)out_size;
    const float* x    = (const float*)d_in[0];
    const float* W_B  = (const float*)d_in[1];
    const float* b_B  = (const float*)d_in[2];
    const float* W_C  = (const float*)d_in[3];
    const float* b_C  = (const float*)d_in[4];
    const float* W_dt = (const float*)d_in[5];
    const float* b_dt = (const float*)d_in[6];
    const float* logA = (const float*)d_in[7];
    const float* Dsk  = (const float*)d_in[8];
    float* out = (float*)d_out;

    gemm_delta_kernel<<<dim3(DM / 128, MTOT / 128), 256>>>(x, W_dt, b_dt);
    bc_kernel<<<MTOT / 4, 128>>>(x, W_B, b_B, W_C, b_C);
    transpose2_kernel<<<dim3(DM / 32, SEQ / 32, BATCH), dim3(32, 8)>>>(x);
    scan_pass1<<<dim3(DM / 8, CH, BATCH), 128>>>(logA);
    scan_combine<<<(BATCH * DM * DS) / 256, 256>>>();
    scan_pass3<<<dim3(DM / 8, CH, BATCH), 128>>>(logA);
    out_kernel<<<dim3(SEQ / 32, DM / 32, BATCH), dim3(32, 8)>>>(x, Dsk, out);
}

// round 4
// speedup vs baseline: 1.9571x; 1.4326x over previous
#include <cuda_runtime.h>
#include <cuda_bf16.h>
#include <cstdint>

#define BATCH 2
#define SEQ   2048
#define DM    1024
#define DS    16
#define MTOT  (BATCH*SEQ)   // 4096
#define CH    16            // scan chunks
#define CS    (SEQ/CH)      // 128 steps per chunk

// ----------------------------- scratch globals -----------------------------
__device__ float g_delta [MTOT*DM];       // (b,l,d)
__device__ float g_deltaT[BATCH*DM*SEQ];  // (b,d,l)
__device__ float g_xT    [BATCH*DM*SEQ];  // (b,d,l)
__device__ float g_B     [MTOT*DS];       // (b,l,n)
__device__ float g_C     [MTOT*DS];       // (b,l,n)
__device__ float g_yT    [BATCH*DM*SEQ];  // (b,d,l)
__device__ float g_P     [BATCH*DM*CH*DS];
__device__ float g_q     [BATCH*DM*CH*DS];
__device__ float g_h0    [BATCH*DM*CH*DS];
__device__ __nv_bfloat16 g_Xhi[MTOT*DM];
__device__ __nv_bfloat16 g_Xlo[MTOT*DM];
__device__ __nv_bfloat16 g_Whi[DM*DM];
__device__ __nv_bfloat16 g_Wlo[DM*DM];

__device__ __forceinline__ float softplus_f(float z) {
    return fmaxf(z, 0.f) + log1pf(expf(-fabsf(z)));
}

__device__ __forceinline__ uint32_t smem_u32(const void* p) {
    uint32_t a;
    asm("{ .reg .u64 t; cvta.to.shared.u64 t, %1; cvt.u32.u64 %0, t; }"
        : "=r"(a) : "l"(p));
    return a;
}

#define CP16(dst, src) \
    asm volatile("cp.async.cg.shared.global [%0], [%1], 16;" :: "r"(dst), "l"(src))
#define CP_COMMIT() asm volatile("cp.async.commit_group;" ::: "memory")
#define CP_WAIT1()  asm volatile("cp.async.wait_group 1;" ::: "memory")

#define LDSM4(r, addr) \
    asm volatile("ldmatrix.sync.aligned.m8n8.x4.shared.b16 {%0,%1,%2,%3}, [%4];" \
        : "=r"((r)[0]), "=r"((r)[1]), "=r"((r)[2]), "=r"((r)[3]) : "r"(addr))

#define MMA16816(d, a, b0, b1) \
    asm volatile("mma.sync.aligned.m16n8k16.row.col.f32.bf16.bf16.f32 " \
        "{%0,%1,%2,%3}, {%4,%5,%6,%7}, {%8,%9}, {%0,%1,%2,%3};" \
        : "+f"((d)[0]), "+f"((d)[1]), "+f"((d)[2]), "+f"((d)[3]) \
        : "r"((a)[0]), "r"((a)[1]), "r"((a)[2]), "r"((a)[3]), "r"(b0), "r"(b1))

// ---------------------------------------------------------------------------
// Prep: split fp32 -> bf16 (hi, lo)
// ---------------------------------------------------------------------------
__device__ __forceinline__ void split4(float4 v, ushort4& H, ushort4& L) {
    __nv_bfloat16 h;
    h = __float2bfloat16_rn(v.x); H.x = __bfloat16_as_ushort(h);
    L.x = __bfloat16_as_ushort(__float2bfloat16_rn(v.x - __bfloat162float(h)));
    h = __float2bfloat16_rn(v.y); H.y = __bfloat16_as_ushort(h);
    L.y = __bfloat16_as_ushort(__float2bfloat16_rn(v.y - __bfloat162float(h)));
    h = __float2bfloat16_rn(v.z); H.z = __bfloat16_as_ushort(h);
    L.z = __bfloat16_as_ushort(__float2bfloat16_rn(v.z - __bfloat162float(h)));
    h = __float2bfloat16_rn(v.w); H.w = __bfloat16_as_ushort(h);
    L.w = __bfloat16_as_ushort(__float2bfloat16_rn(v.w - __bfloat162float(h)));
}

__global__ void split_x_kernel(const float* __restrict__ src) {
    int i = blockIdx.x * 256 + threadIdx.x;
    float4 v = ((const float4*)src)[i];
    ushort4 H, L; split4(v, H, L);
    ((ushort4*)g_Xhi)[i] = H;
    ((ushort4*)g_Xlo)[i] = L;
}
__global__ void split_w_kernel(const float* __restrict__ src) {
    int i = blockIdx.x * 256 + threadIdx.x;
    float4 v = ((const float4*)src)[i];
    ushort4 H, L; split4(v, H, L);
    ((ushort4*)g_Whi)[i] = H;
    ((ushort4*)g_Wlo)[i] = L;
}

// ---------------------------------------------------------------------------
// Kernel 1: delta = softplus(X @ W^T + b) via mma.sync bf16 3-term split.
// 128x128 CTA tile, BK=32, 2-stage cp.async double buffer, ldmatrix frags.
// 96 K-iterations: pass 0 hi@hi, pass 1 hi@lo, pass 2 lo@hi (one fp32 acc).
// smem rows padded to 40 bf16 (80B): row-start bank-group = 5r mod 8 (perfect
// permutation over 8 consecutive rows -> conflict-free ldmatrix).
// ---------------------------------------------------------------------------
#define SROW 40
#define SBUF (128 * SROW)   // elems per buffer

__global__ __launch_bounds__(256) void gemm_mma_kernel(const float* __restrict__ bias)
{
    __shared__ __nv_bfloat16 sA[2][SBUF];
    __shared__ __nv_bfloat16 sB[2][SBUF];

    const int tid  = threadIdx.x;
    const int wid  = tid >> 5;
    const int lane = tid & 31;
    const int wm   = wid >> 1;     // 0..3
    const int wn   = wid & 1;      // 0..1
    const int m0   = blockIdx.y * 128;
    const int n0   = blockIdx.x * 128;

    const uint32_t sAb = smem_u32(sA);
    const uint32_t sBb = smem_u32(sB);

    float acc[2][8][4];
#pragma unroll
    for (int i = 0; i < 2; i++)
#pragma unroll
        for (int j = 0; j < 8; j++)
#pragma unroll
            for (int k = 0; k < 4; k++) acc[i][j][k] = 0.f;

    // tile loader: iteration it -> (pass, k-chunk); 16B cp.async per unit
    auto load_tile = [&](int it, int buf) {
        const int p  = it >> 5;
        const size_t kb = (size_t)(it & 31) * 64;   // byte offset along K
        const char* Ab = (const char*)((p < 2)  ? g_Xhi : g_Xlo);
        const char* Bb = (const char*)((p == 1) ? g_Wlo : g_Whi);
#pragma unroll
        for (int i = 0; i < 2; i++) {
            const int chunk = tid + i * 256;
            const int row = chunk >> 2, c = chunk & 3;
            const char* srcA = Ab + (((size_t)(m0 + row)) << 11) + kb + c * 16;
            const char* srcB = Bb + (((size_t)(n0 + row)) << 11) + kb + c * 16;
            const uint32_t so = (uint32_t)buf * (SBUF * 2) + row * (SROW * 2) + c * 16;
            CP16(sAb + so, srcA);
            CP16(sBb + so, srcB);
        }
    };

    load_tile(0, 0); CP_COMMIT();
    load_tile(1, 1); CP_COMMIT();

    for (int it = 0; it < 96; it++) {
        CP_WAIT1();
        __syncthreads();
        const int buf = it & 1;
        const uint32_t ab = sAb + (uint32_t)buf * (SBUF * 2);
        const uint32_t bb = sBb + (uint32_t)buf * (SBUF * 2);

#pragma unroll
        for (int ks = 0; ks < 2; ks++) {
            uint32_t afr[2][4], bfr[4][4];
#pragma unroll
            for (int mi = 0; mi < 2; mi++) {
                const int row = wm * 32 + mi * 16 + (lane & 7) + ((lane >> 3) & 1) * 8;
                LDSM4(afr[mi], ab + row * (SROW * 2) + ks * 32 + (lane >> 4) * 16);
            }
#pragma unroll
            for (int ni = 0; ni < 4; ni++) {
                const int row = wn * 64 + ni * 16 + (lane & 7) + ((lane >> 4) << 3);
                LDSM4(bfr[ni], bb + row * (SROW * 2) + ks * 32 + ((lane >> 3) & 1) * 16);
            }
#pragma unroll
            for (int mi = 0; mi < 2; mi++)
#pragma unroll
                for (int nj = 0; nj < 8; nj++)
                    MMA16816(acc[mi][nj], afr[mi], bfr[nj >> 1][(nj & 1) * 2],
                             bfr[nj >> 1][(nj & 1) * 2 + 1]);
        }
        __syncthreads();
        if (it + 2 < 96) load_tile(it + 2, buf);
        CP_COMMIT();
    }

    // epilogue: bias + softplus, float2 stores
    const int tq = lane >> 2, tr = lane & 3;
#pragma unroll
    for (int mi = 0; mi < 2; mi++) {
        const int r0 = m0 + wm * 32 + mi * 16 + tq;
#pragma unroll
        for (int nj = 0; nj < 8; nj++) {
            const int c = n0 + wn * 64 + nj * 8 + tr * 2;
            const float bx = __ldg(bias + c), by = __ldg(bias + c + 1);
            float2 v0, v1;
            v0.x = softplus_f(acc[mi][nj][0] + bx);
            v0.y = softplus_f(acc[mi][nj][1] + by);
            v1.x = softplus_f(acc[mi][nj][2] + bx);
            v1.y = softplus_f(acc[mi][nj][3] + by);
            *(float2*)(g_delta + (size_t)r0 * DM + c)       = v0;
            *(float2*)(g_delta + (size_t)(r0 + 8) * DM + c) = v1;
        }
    }
}

// ---------------------------------------------------------------------------
// Kernel 2: B/C projections -> (b, l, n) layout.
// ---------------------------------------------------------------------------
__global__ __launch_bounds__(128) void bc_kernel(
    const float* __restrict__ X,
    const float* __restrict__ WB, const float* __restrict__ bB,
    const float* __restrict__ WC, const float* __restrict__ bC)
{
    const int warp = threadIdx.x >> 5;
    const int lane = threadIdx.x & 31;
    const int m = blockIdx.x * 4 + warp;

    float accB[16], accC[16];
#pragma unroll
    for (int j = 0; j < 16; j++) { accB[j] = 0.f; accC[j] = 0.f; }

    const float4* X4  = (const float4*)(X + (size_t)m * DM);
    const float4* WB4 = (const float4*)WB;
    const float4* WC4 = (const float4*)WC;

    for (int k0 = 0; k0 < DM / 4; k0 += 32) {
        float4 xv = X4[k0 + lane];
#pragma unroll
        for (int j = 0; j < 16; j++) {
            float4 w = WB4[j * (DM / 4) + k0 + lane];
            accB[j] += xv.x * w.x + xv.y * w.y + xv.z * w.z + xv.w * w.w;
            float4 wc = WC4[j * (DM / 4) + k0 + lane];
            accC[j] += xv.x * wc.x + xv.y * wc.y + xv.z * wc.z + xv.w * wc.w;
        }
    }

    float res = 0.f;
#pragma unroll
    for (int j = 0; j < 32; j++) {
        float p = (j < 16) ? accB[j] : accC[j - 16];
#pragma unroll
        for (int o = 16; o > 0; o >>= 1)
            p += __shfl_xor_sync(0xffffffffu, p, o);
        if (lane == j) res = p;
    }
    if (lane < 16)
        g_B[(size_t)m * DS + lane] = res + bB[lane];
    else
        g_C[(size_t)m * DS + (lane - 16)] = res + bC[lane - 16];
}

// ---------------------------------------------------------------------------
// Kernel 3: transpose delta and x from (b,l,d) -> (b,d,l)
// ---------------------------------------------------------------------------
__global__ void transpose2_kernel(const float* __restrict__ X)
{
    __shared__ float t0[32][33];
    __shared__ float t1[32][33];
    const int b  = blockIdx.z;
    const int d0 = blockIdx.x * 32;
    const int l0 = blockIdx.y * 32;
    const int tx = threadIdx.x, ty = threadIdx.y;

#pragma unroll
    for (int i = 0; i < 32; i += 8) {
        size_t src = ((size_t)(b * SEQ + l0 + ty + i)) * DM + d0 + tx;
        t0[ty + i][tx] = g_delta[src];
        t1[ty + i][tx] = X[src];
    }
    __syncthreads();
#pragma unroll
    for (int i = 0; i < 32; i += 8) {
        size_t dst = ((size_t)(b * DM + d0 + ty + i)) * SEQ + l0 + tx;
        g_deltaT[dst] = t0[tx][ty + i];
        g_xT[dst]     = t1[tx][ty + i];
    }
}

// ---------------------------------------------------------------------------
// Scan pass 1: per chunk, P = prod(dA), q = h(end | h0=0).
// ---------------------------------------------------------------------------
__global__ __launch_bounds__(128) void scan_pass1(const float* __restrict__ logA)
{
    __shared__ __align__(16) float sB[CS * DS];

    const int b  = blockIdx.z;
    const int c  = blockIdx.y;
    const int d0 = blockIdx.x * 8;
    const int g  = threadIdx.x >> 4;
    const int n  = threadIdx.x & 15;
    const int d  = d0 + g;
    const int bd = b * DM + d;

    {
        const float4* src = (const float4*)(g_B + ((size_t)b * SEQ + c * CS) * DS);
        float4* dst = (float4*)sB;
        for (int i = threadIdx.x; i < CS * DS / 4; i += 128) dst[i] = src[i];
    }
    __syncthreads();

    const float A = -expf(logA[d * DS + n]);
    const float4* dp = (const float4*)(g_deltaT + (size_t)bd * SEQ + c * CS);
    const float4* xp = (const float4*)(g_xT     + (size_t)bd * SEQ + c * CS);

    float h = 0.f, P = 1.f;
    for (int q4 = 0; q4 < CS / 4; q4++) {
        float4 dv = dp[q4], xv = xp[q4];
        const int l = q4 * 4;
        float b0 = sB[(l + 0) * DS + n], b1 = sB[(l + 1) * DS + n];
        float b2 = sB[(l + 2) * DS + n], b3 = sB[(l + 3) * DS + n];
        float dA;
        dA = __expf(dv.x * A); P *= dA; h = fmaf(dA, h, dv.x * xv.x * b0);
        dA = __expf(dv.y * A); P *= dA; h = fmaf(dA, h, dv.y * xv.y * b1);
        dA = __expf(dv.z * A); P *= dA; h = fmaf(dA, h, dv.z * xv.z * b2);
        dA = __expf(dv.w * A); P *= dA; h = fmaf(dA, h, dv.w * xv.w * b3);
    }
    const size_t idx = ((size_t)bd * CH + c) * DS + n;
    g_P[idx] = P;
    g_q[idx] = h;
}

// ---------------------------------------------------------------------------
// Scan pass 2: combine chunk summaries -> h0 per chunk.
// ---------------------------------------------------------------------------
__global__ void scan_combine()
{
    const int t = blockIdx.x * 256 + threadIdx.x;
    const int bd = t >> 4;
    const int n  = t & 15;
    float h = 0.f;
    for (int c = 0; c < CH; c++) {
        const size_t idx = ((size_t)bd * CH + c) * DS + n;
        g_h0[idx] = h;
        h = fmaf(g_P[idx], h, g_q[idx]);
    }
}

// ---------------------------------------------------------------------------
// Scan pass 3: rescan from h0, emit y.
// ---------------------------------------------------------------------------
__global__ __launch_bounds__(128) void scan_pass3(const float* __restrict__ logA)
{
    __shared__ __align__(16) float sB[CS * DS];
    __shared__ __align__(16) float sC[CS * DS];

    const int b  = blockIdx.z;
    const int c  = blockIdx.y;
    const int d0 = blockIdx.x * 8;
    const int g  = threadIdx.x >> 4;
    const int n  = threadIdx.x & 15;
    const int d  = d0 + g;
    const int bd = b * DM + d;

    {
        const float4* srcB = (const float4*)(g_B + ((size_t)b * SEQ + c * CS) * DS);
        const float4* srcC = (const float4*)(g_C + ((size_t)b * SEQ + c * CS) * DS);
        float4* dstB = (float4*)sB;
        float4* dstC = (float4*)sC;
        for (int i = threadIdx.x; i < CS * DS / 4; i += 128) {
            dstB[i] = srcB[i];
            dstC[i] = srcC[i];
        }
    }
    __syncthreads();

    const float A = -expf(logA[d * DS + n]);
    const float4* dp = (const float4*)(g_deltaT + (size_t)bd * SEQ + c * CS);
    const float4* xp = (const float4*)(g_xT     + (size_t)bd * SEQ + c * CS);
    float4*       yp = (float4*)(g_yT           + (size_t)bd * SEQ + c * CS);

    float h = g_h0[((size_t)bd * CH + c) * DS + n];

#define SSM_STEP(DV, XV, BV, CV, YO)                                   \
    {                                                                  \
        float dA = __expf((DV) * A);                                   \
        h = fmaf(dA, h, (DV) * (XV) * (BV));                           \
        float p = h * (CV);                                            \
        p += __shfl_xor_sync(0xffffffffu, p, 8);                       \
        p += __shfl_xor_sync(0xffffffffu, p, 4);                       \
        p += __shfl_xor_sync(0xffffffffu, p, 2);                       \
        p += __shfl_xor_sync(0xffffffffu, p, 1);                       \
        (YO) = p;                                                      \
    }

    for (int q4 = 0; q4 < CS / 4; q4++) {
        float4 dv = dp[q4], xv = xp[q4];
        const int l = q4 * 4;
        float b0 = sB[(l + 0) * DS + n], b1 = sB[(l + 1) * DS + n];
        float b2 = sB[(l + 2) * DS + n], b3 = sB[(l + 3) * DS + n];
        float c0 = sC[(l + 0) * DS + n], c1 = sC[(l + 1) * DS + n];
        float c2 = sC[(l + 2) * DS + n], c3 = sC[(l + 3) * DS + n];
        float4 y;
        SSM_STEP(dv.x, xv.x, b0, c0, y.x);
        SSM_STEP(dv.y, xv.y, b1, c1, y.y);
        SSM_STEP(dv.z, xv.z, b2, c2, y.z);
        SSM_STEP(dv.w, xv.w, b3, c3, y.w);
        if (n == 0) yp[q4] = y;
    }
#undef SSM_STEP
}

// ---------------------------------------------------------------------------
// Kernel 5: out[b,l,d] = yT[b,d,l] + x[b,l,d] * D_skip[d]
// ---------------------------------------------------------------------------
__global__ void out_kernel(const float* __restrict__ X,
                           const float* __restrict__ Dskip,
                           float* __restrict__ out)
{
    __shared__ float t[32][33];
    const int b  = blockIdx.z;
    const int l0 = blockIdx.x * 32;
    const int d0 = blockIdx.y * 32;
    const int tx = threadIdx.x, ty = threadIdx.y;

#pragma unroll
    for (int i = 0; i < 32; i += 8)
        t[ty + i][tx] = g_yT[((size_t)(b * DM + d0 + ty + i)) * SEQ + l0 + tx];
    __syncthreads();
    const float dsk = Dskip[d0 + tx];
#pragma unroll
    for (int i = 0; i < 32; i += 8) {
        size_t idx = ((size_t)(b * SEQ + l0 + ty + i)) * DM + d0 + tx;
        out[idx] = t[tx][ty + i] + X[idx] * dsk;
    }
}

// ---------------------------------------------------------------------------
extern "C" void kernel_launch(void* const* d_in, const int* in_sizes, int n_in,
                              void* d_out, int out_size)
{
    (void)in_sizes; (void)n_in; (void)out_size;
    const float* x    = (const float*)d_in[0];
    const float* W_B  = (const float*)d_in[1];
    const float* b_B  = (const float*)d_in[2];
    const float* W_C  = (const float*)d_in[3];
    const float* b_C  = (const float*)d_in[4];
    const float* W_dt = (const float*)d_in[5];
    const float* b_dt = (const float*)d_in[6];
    const float* logA = (const float*)d_in[7];
    const float* Dsk  = (const float*)d_in[8];
    float* out = (float*)d_out;

    split_x_kernel<<<(MTOT * DM / 4) / 256, 256>>>(x);
    split_w_kernel<<<(DM * DM / 4) / 256, 256>>>(W_dt);
    gemm_mma_kernel<<<dim3(DM / 128, MTOT / 128), 256>>>(b_dt);
    bc_kernel<<<MTOT / 4, 128>>>(x, W_B, b_B, W_C, b_C);
    transpose2_kernel<<<dim3(DM / 32, SEQ / 32, BATCH), dim3(32, 8)>>>(x);
    scan_pass1<<<dim3(DM / 8, CH, BATCH), 128>>>(logA);
    scan_combine<<<(BATCH * DM * DS) / 256, 256>>>();
    scan_pass3<<<dim3(DM / 8, CH, BATCH), 128>>>(logA);
    out_kernel<<<dim3(SEQ / 32, DM / 32, BATCH), dim3(32, 8)>>>(x, Dsk, out);
}